// round 4
// baseline (speedup 1.0000x reference)
#include <cuda_runtime.h>
#include <math.h>

#define Bn     2
#define NBOX   32
#define NTH    4
#define ROIW   28
#define Hh     768
#define Ww     704
#define HWp    (Hh*Ww)          // 540672
#define NSTUFF 6
#define NCLS   10
#define Lout   39               // 1 + NSTUFF + NBOX

struct BoxMeta {
    int   iy0, ix0, iy1, ix1;     // in2 rect (half-open)
    int   py0, px0, py1, px1;     // paste/inside rect (half-open)
    float fy0, fx0;               // floor(bbx0), floor(bbx1) as float
    float sysc, sxsc;             // 28/h, 28/w
    int   semc;                   // 6 + cls
    int   mskoff;                 // float offset of selected 28x28 mask
    int   pad0, pad1;
};

__device__ BoxMeta       g_boxes[Bn*NBOX];
__device__ int           g_counts[Bn][NBOX*NCLS];
__device__ int           g_sflag[Bn][NSTUFF];
__device__ float         g_lut[Bn][NSTUFF+NBOX];   // seam values as float
__device__ unsigned char g_pp[Bn*HWp];

__device__ __forceinline__ float sigm(float x) {
    if (x >= 0.0f) return 1.0f / (1.0f + expf(-x));
    float e = expf(x);
    return e / (1.0f + e);
}

// ---------------- kernel 0: zero hists + box metadata ----------------
__global__ void k_init(const float* __restrict__ bbx, const int* __restrict__ cls) {
    int t = threadIdx.x;
    for (int i = t; i < Bn*NBOX*NCLS; i += blockDim.x) ((int*)g_counts)[i] = 0;
    if (t < Bn*NSTUFF) ((int*)g_sflag)[t] = 0;
    if (t < Bn*NBOX) {
        float b0 = bbx[t*4+0], b1 = bbx[t*4+1], b2 = bbx[t*4+2], b3 = bbx[t*4+3];
        int y0f = (int)floorf(b0), x0f = (int)floorf(b1);
        int y1f = (int)floorf(b2), x1f = (int)floorf(b3);
        BoxMeta m;
        m.iy0 = y0f;  m.ix0 = x0f;
        m.iy1 = (int)(rintf(b2) + 1.0f);
        m.ix1 = (int)(rintf(b3) + 1.0f);
        m.py0 = max(y0f, 0);      m.px0 = max(x0f, 0);
        m.py1 = min(y1f + 1, Hh); m.px1 = min(x1f + 1, Ww);
        float hh = (float)max(y1f - y0f + 1, 1);
        float ww = (float)max(x1f - x0f + 1, 1);
        m.sysc = 28.0f / hh; m.sxsc = 28.0f / ww;
        m.fy0 = (float)y0f;  m.fx0 = (float)x0f;
        int c = cls[t];
        c = max(0, min(c, NTH-1));
        m.semc = NSTUFF + c;
        m.mskoff = (t * NTH + c) * (ROIW * ROIW);
        m.pad0 = 0; m.pad1 = 0;
        g_boxes[t] = m;
    }
}

// ---------------- pass A: per-pixel argmaxes + histograms ----------------
__global__ void __launch_bounds__(256) k_passA(const float* __restrict__ sem,
                                               const float* __restrict__ roi) {
    __shared__ BoxMeta sb[NBOX];
    __shared__ int scnt[NBOX*NCLS];
    __shared__ int sfl[NSTUFF];

    const int BPB = HWp / 256;                 // 2112 blocks per batch
    int b   = blockIdx.x / BPB;
    int pix = (blockIdx.x % BPB) * 256 + threadIdx.x;
    int t   = threadIdx.x;

    for (int i = t; i < NBOX*NCLS; i += 256) scnt[i] = 0;
    if (t < NSTUFF) sfl[t] = 0;
    if (t < NBOX)   sb[t] = g_boxes[b*NBOX + t];
    __syncthreads();

    int y = pix / Ww, x = pix % Ww;
    const float* semb = sem + (size_t)b * NCLS * HWp + pix;

    float v0   = semb[0];
    float smax = v0; int sp = 0;     // sem_pred over 10 channels
    float best = v0; int bi = 0;     // po_pred (channels 0..5 first)
    #pragma unroll
    for (int c = 1; c < NCLS; ++c) {
        float u = semb[(size_t)c * HWp];
        if (u > smax) { smax = u; sp = c; }
        if (c < NSTUFF && u > best) { best = u; bi = c; }
    }

    // constant combined value for a box that does not cover this pixel
    const float CNEG = (2.0f * sigm(-100.0f)) * (-200.0f);

    #pragma unroll 1
    for (int n = 0; n < NBOX; ++n) {
        const BoxMeta& m = sb[n];
        float val;
        if (y >= m.iy0 && y < m.iy1 && x >= m.ix0 && x < m.ix1) {
            float pi = semb[(size_t)m.semc * HWp];
            float pm;
            if (y >= m.py0 && y < m.py1 && x >= m.px0 && x < m.px1) {
                float sy = ((float)y - m.fy0 + 0.5f) * m.sysc - 0.5f;
                sy = fminf(fmaxf(sy, 0.0f), 27.0f);
                float sx = ((float)x - m.fx0 + 0.5f) * m.sxsc - 0.5f;
                sx = fminf(fmaxf(sx, 0.0f), 27.0f);
                int yl = (int)sy, xl = (int)sx;
                int yh = min(yl + 1, 27), xh = min(xl + 1, 27);
                float wy = sy - (float)yl, wx = sx - (float)xl;
                const float* mk = roi + m.mskoff;
                float a = mk[yl*ROIW + xl], bq = mk[yl*ROIW + xh];
                float cq = mk[yh*ROIW + xl], dq = mk[yh*ROIW + xh];
                float r0 = a  * (1.0f - wy) + cq * wy;
                float r1 = bq * (1.0f - wy) + dq * wy;
                pm = r0 * (1.0f - wx) + r1 * wx;
            } else {
                pm = -100.0f;
            }
            val = (sigm(pi) + sigm(pm)) * (pi + pm);
        } else {
            val = CNEG;
        }
        if (val > best) { best = val; bi = NSTUFF + n; }
    }

    g_pp[b*HWp + pix] = (unsigned char)bi;
    if (bi >= NSTUFF) atomicAdd(&scnt[(bi - NSTUFF)*NCLS + sp], 1);
    else              sfl[bi] = 1;
    __syncthreads();

    for (int i = t; i < NBOX*NCLS; i += 256) {
        int v = scnt[i];
        if (v) atomicAdd(&g_counts[b][i], v);
    }
    if (t < NSTUFF && sfl[t]) g_sflag[b][t] = 1;
}

// ---------------- pass B: per-batch label logic (tiny, serial) ----------------
// NOTE: outputs written as FLOAT32 (harness __output__ dtype).
__global__ void k_passB(const int* __restrict__ cls, float* __restrict__ out) {
    int b = threadIdx.x;
    if (b >= Bn) return;

    int  idxv[NBOX], semval[NBOX];
    bool present[NBOX], tostuff[NBOX];
    int run = 0;
    for (int n = 0; n < NBOX; ++n) {
        int s = 0, mmx = 0, mj = 0;
        for (int c = 0; c < NCLS; ++c) {
            int v = g_counts[b][n*NCLS + c];
            s += v;
            if (v > mmx) { mmx = v; mj = c; }
        }
        bool pr = s > 0;
        present[n] = pr;
        if (pr) run++;
        idxv[n] = run - 1;
        int thing = cls[b*NBOX + n] + NSTUFF;
        bool ts = (mj != thing) && (2*mmx >= max(s, 1)) && (mj < NSTUFF);
        tostuff[n] = ts;
        semval[n]  = ts ? mj : thing;
    }

    bool sp_[NSTUFF];
    for (int s = 0; s < NSTUFF; ++s) sp_[s] = (g_sflag[b][s] != 0);
    for (int n = 0; n < NBOX; ++n)
        if (present[n] && tostuff[n]) sp_[semval[n]] = true;

    int s_rank[NSTUFF]; int r = 0;
    for (int s = 0; s < NSTUFF; ++s) { if (sp_[s]) r++; s_rank[s] = r - 1; }
    int nstuff = r;

    bool ip[NBOX];
    for (int i = 0; i < NBOX; ++i) ip[i] = false;
    for (int n = 0; n < NBOX; ++n)
        if (present[n] && !tostuff[n]) ip[idxv[n]] = true;
    int i_rank[NBOX]; int r2 = 0;
    for (int i = 0; i < NBOX; ++i) { if (ip[i]) r2++; i_rank[i] = r2 - 1; }

    for (int c = 0; c < NSTUFF; ++c) g_lut[b][c] = (float)(1 + s_rank[c]);
    for (int n = 0; n < NBOX; ++n) {
        int v = 0;
        if (present[n])
            v = tostuff[n] ? (1 + s_rank[semval[n]])
                           : (1 + nstuff + i_rank[idxv[n]]);
        g_lut[b][NSTUFF + n] = (float)v;
    }

    int co[Lout];
    for (int i = 0; i < Lout; ++i) co[i] = 255;
    for (int s = 0; s < NSTUFF; ++s)
        if (sp_[s]) co[1 + s_rank[s]] = s;
    for (int n = 0; n < NBOX; ++n)
        if (present[n] && !tostuff[n]) co[1 + nstuff + i_rank[idxv[n]]] = semval[n];

    float* cbase = out + Bn*HWp + b*Lout;
    for (int i = 0; i < Lout; ++i) cbase[i] = (float)co[i];
    float* ibase = out + Bn*HWp + Bn*Lout + b*Lout;
    for (int i = 0; i < Lout; ++i) ibase[i] = 0.0f;
}

// ---------------- pass C: seam remap (vectorized, float output) ----------------
__global__ void __launch_bounds__(256) k_passC(float* __restrict__ out) {
    __shared__ float slut[Bn*(NSTUFF+NBOX)];
    int t = threadIdx.x;
    if (t < Bn*(NSTUFF+NBOX)) slut[t] = ((const float*)g_lut)[t];
    __syncthreads();

    int qid = blockIdx.x * 256 + t;          // quad of 4 pixels
    const int QPB = HWp / 4;                 // quads per batch (batch-aligned)
    int b = qid / QPB;
    uchar4 p = ((const uchar4*)g_pp)[qid];
    int base = b * (NSTUFF+NBOX);
    float4 o;
    o.x = slut[base + p.x];
    o.y = slut[base + p.y];
    o.z = slut[base + p.z];
    o.w = slut[base + p.w];
    ((float4*)out)[qid] = o;
}

extern "C" void kernel_launch(void* const* d_in, const int* in_sizes, int n_in,
                              void* d_out, int out_size) {
    // Bind inputs by element count (unique per input) — robust to metadata ordering.
    const float* sem = nullptr;   // 2*10*768*704 = 10813440
    const float* roi = nullptr;   // 2*32*4*28*28 = 200704
    const float* bbx = nullptr;   // 2*32*4       = 256
    const int*   cls = nullptr;   // 2*32         = 64
    for (int i = 0; i < n_in; ++i) {
        switch (in_sizes[i]) {
            case 10813440: sem = (const float*)d_in[i]; break;
            case 200704:   roi = (const float*)d_in[i]; break;
            case 256:      bbx = (const float*)d_in[i]; break;
            case 64:       cls = (const int*)d_in[i];   break;
            default: break; // img_size (2 elems) unused
        }
    }
    float* out = (float*)d_out;

    k_init <<<1, 128>>>(bbx, cls);
    k_passA<<<Bn*HWp/256, 256>>>(sem, roi);
    k_passB<<<1, 32>>>(cls, out);
    k_passC<<<(Bn*HWp/4)/256, 256>>>(out);
}